// round 5
// baseline (speedup 1.0000x reference)
#include <cuda_runtime.h>
#include <cuda_fp16.h>
#include <math.h>
#include <stdint.h>

// ---------------- problem constants ----------------
namespace {
constexpr int cB  = 2;
constexpr int cS  = 2048;
constexpr int cH  = 3072;
constexpr int cNH = 16;
constexpr int cHD = 256;
constexpr int cQSZ  = cNH * cHD;            // 4096
constexpr int cQKV  = 3 * cQSZ;             // 12288
constexpr int cM    = cB * cS;              // 4096 rows
}

// ---------------- scratch ----------------
__device__ float g_qkv[(size_t)cM * cQKV];          // fp32, = 64 * true qkv
__device__ __half g_hid_h[(size_t)cM * cH];         // hidden fp16 (single)
__device__ __half g_w1_h[(size_t)cQKV * cH];        // (64*Wqkv)^T hi
__device__ __half g_w1_l[(size_t)cQKV * cH];        // lo
__device__ __half g_at_h[(size_t)cM * cQSZ];        // attn out hi
__device__ __half g_at_l[(size_t)cM * cQSZ];
__device__ __half g_w2_h[(size_t)cH * cQSZ];        // (64*Wo)^T hi
__device__ __half g_w2_l[(size_t)cH * cQSZ];
// head-major [bh][s][d]
__device__ __half g_qh[(size_t)cM * cQSZ];          // Q single (scaled)
__device__ __half g_kh[(size_t)cM * cQSZ];
__device__ __half g_kl[(size_t)cM * cQSZ];
__device__ __half g_vh[(size_t)cM * cQSZ];
__device__ __half g_vl[(size_t)cM * cQSZ];
__device__ double g_invf[128];

// ---------------- helpers (base ISA, compute_103-safe) ----------------
__device__ __forceinline__ uint32_t smem_u32(const void* p) {
  uint32_t a;
  asm("{ .reg .u64 t; cvta.to.shared.u64 t, %1; cvt.u32.u64 %0, t; }"
      : "=r"(a) : "l"(p));
  return a;
}
#define CP_ASYNC16(dst, src) \
  asm volatile("cp.async.cg.shared.global [%0], [%1], 16;" :: "r"(dst), "l"(src))
#define CP_COMMIT() asm volatile("cp.async.commit_group;" ::: "memory")
#define CP_WAIT(n)  asm volatile("cp.async.wait_group %0;" :: "n"(n) : "memory")
#define LDSM4(r0, r1, r2, r3, addr) \
  asm volatile("ldmatrix.sync.aligned.m8n8.x4.shared.b16 {%0,%1,%2,%3}, [%4];" \
               : "=r"(r0), "=r"(r1), "=r"(r2), "=r"(r3) : "r"(addr))
#define LDSM4T(r0, r1, r2, r3, addr) \
  asm volatile("ldmatrix.sync.aligned.m8n8.x4.trans.shared.b16 {%0,%1,%2,%3}, [%4];" \
               : "=r"(r0), "=r"(r1), "=r"(r2), "=r"(r3) : "r"(addr))

__device__ __forceinline__ void mma16816(float* d, const uint32_t* a,
                                         const uint32_t* b) {
  asm volatile(
      "mma.sync.aligned.m16n8k16.row.col.f32.f16.f16.f32 "
      "{%0,%1,%2,%3}, {%4,%5,%6,%7}, {%8,%9}, {%0,%1,%2,%3};"
      : "+f"(d[0]), "+f"(d[1]), "+f"(d[2]), "+f"(d[3])
      : "r"(a[0]), "r"(a[1]), "r"(a[2]), "r"(a[3]), "r"(b[0]), "r"(b[1]));
}

__device__ __forceinline__ __half2 mk_h2(float a, float b) {
  return __halves2half2(__float2half(a), __float2half(b));
}

// ---------------- hidden fp32 -> fp16 single ----------------
__global__ __launch_bounds__(256) void conv_kernel(
    const float* __restrict__ x, __half* __restrict__ h, int n4) {
  int i = blockIdx.x * 256 + threadIdx.x;
  if (i >= n4) return;
  float4 v = ((const float4*)x)[i];
  ((__half2*)h)[2 * i]     = mk_h2(v.x, v.y);
  ((__half2*)h)[2 * i + 1] = mk_h2(v.z, v.w);
}

// ---------------- transpose + scale(64) + split hi/lo ----------------
__global__ __launch_bounds__(256) void tsplit_kernel(
    const float* __restrict__ W, __half* __restrict__ Th,
    __half* __restrict__ Tl, int K, int N) {
  __shared__ float sm[32][33];
  int n0 = blockIdx.x * 32, k0 = blockIdx.y * 32;
  int tx = threadIdx.x & 31, ty = threadIdx.x >> 5;
  #pragma unroll
  for (int q = 0; q < 4; q++)
    sm[ty + 8 * q][tx] = W[(size_t)(k0 + ty + 8 * q) * N + n0 + tx];
  __syncthreads();
  #pragma unroll
  for (int q = 0; q < 4; q++) {
    float x = sm[tx][ty + 8 * q] * 64.0f;
    __half h = __float2half(x);
    float lo = x - __half2float(h);
    size_t o = (size_t)(n0 + ty + 8 * q) * K + k0 + tx;
    Th[o] = h;
    Tl[o] = __float2half(lo);
  }
}

// ---------------- HMMA GEMM: C = escale * A[M,K] * Bt[N,K]^T --------------
// AP=1: A single fp16, 2 passes (Ah*Bh + Ah*Bl).
// AP=2: A hi/lo,      3 passes (+ Al*Bh).
constexpr int BM = 128, BN = 128, BKt = 32;
constexpr int AST = 40;
constexpr int PARTE = 128 * AST;

template <int AP>
__global__ __launch_bounds__(256, 2) void gemm_hmma(
    const __half* __restrict__ Ah, const __half* __restrict__ Al,
    const __half* __restrict__ Bh, const __half* __restrict__ Bl,
    float* __restrict__ C, int M, int N, int K, float escale) {
  constexpr int PARTS = 2 + AP;
  constexpr int BUFB = PARTS * PARTE * 2;   // bytes per stage
  extern __shared__ __half smb[];
  const uint32_t sbase = smem_u32(smb);
  const int tid = threadIdx.x, lane = tid & 31, wid = tid >> 5;
  const int m0 = blockIdx.y * BM, n0 = blockIdx.x * BN;
  const int wm = (wid & 1) * 64, wn = (wid >> 1) * 32;

  float acc[4][4][4];
  #pragma unroll
  for (int i = 0; i < 4; i++)
    #pragma unroll
    for (int j = 0; j < 4; j++)
      #pragma unroll
      for (int q = 0; q < 4; q++) acc[i][j][q] = 0.0f;

  const int T = K / BKt;
  int ldr[2], ldc[2];
  #pragma unroll
  for (int i = 0; i < 2; i++) {
    int idx = tid + i * 256;
    ldr[i] = idx >> 2;
    ldc[i] = idx & 3;
  }

  #define ISSUE(t)                                                          \
    do {                                                                    \
      int k0_ = (t) * BKt;                                                  \
      uint32_t db_ = sbase + ((t) & 1) * BUFB;                              \
      _Pragma("unroll")                                                     \
      for (int i_ = 0; i_ < 2; i_++) {                                      \
        int r_ = ldr[i_], c_ = ldc[i_];                                     \
        size_t ao_ = (size_t)(m0 + r_) * K + k0_ + c_ * 8;                  \
        size_t bo_ = (size_t)(n0 + r_) * K + k0_ + c_ * 8;                  \
        uint32_t d_ = db_ + (r_ * AST + c_ * 8) * 2;                        \
        CP_ASYNC16(d_, Ah + ao_);                                           \
        if (AP == 2) CP_ASYNC16(d_ + PARTE * 2, Al + ao_);                  \
        CP_ASYNC16(d_ + AP * PARTE * 2, Bh + bo_);                          \
        CP_ASYNC16(d_ + (AP + 1) * PARTE * 2, Bl + bo_);                    \
      }                                                                     \
    } while (0)

  ISSUE(0);
  CP_COMMIT();

  for (int t = 0; t < T; t++) {
    if (t + 1 < T) {
      ISSUE(t + 1);
      CP_COMMIT();
      CP_WAIT(1);
    } else {
      CP_WAIT(0);
    }
    __syncthreads();

    uint32_t base = sbase + (t & 1) * BUFB;
    const uint32_t pAh = base;
    const uint32_t pAl = base + PARTE * 2;
    const uint32_t pBh = base + AP * PARTE * 2;
    const uint32_t pBl = pBh + PARTE * 2;

    #pragma unroll
    for (int ks = 0; ks < 2; ks++) {
      const int kb = ks * 16;
      uint32_t ah[4][4], al[4][4], bh[4][2], bl[4][2];
      #pragma unroll
      for (int mt = 0; mt < 4; mt++) {
        int r = wm + mt * 16 + (lane & 15);
        int c = kb + ((lane >> 4) << 3);
        uint32_t off = (uint32_t)(r * AST + c) * 2;
        LDSM4(ah[mt][0], ah[mt][1], ah[mt][2], ah[mt][3], pAh + off);
        if (AP == 2)
          LDSM4(al[mt][0], al[mt][1], al[mt][2], al[mt][3], pAl + off);
      }
      #pragma unroll
      for (int p = 0; p < 2; p++) {
        int g = lane >> 3;
        int r = wn + (p * 2 + (g >> 1)) * 8 + (lane & 7);
        int c = kb + ((g & 1) << 3);
        uint32_t off = (uint32_t)(r * AST + c) * 2;
        LDSM4(bh[2 * p][0], bh[2 * p][1], bh[2 * p + 1][0], bh[2 * p + 1][1],
              pBh + off);
        LDSM4(bl[2 * p][0], bl[2 * p][1], bl[2 * p + 1][0], bl[2 * p + 1][1],
              pBl + off);
      }
      #pragma unroll
      for (int mt = 0; mt < 4; mt++)
        #pragma unroll
        for (int nt = 0; nt < 4; nt++) mma16816(acc[mt][nt], ah[mt], bh[nt]);
      #pragma unroll
      for (int mt = 0; mt < 4; mt++)
        #pragma unroll
        for (int nt = 0; nt < 4; nt++) mma16816(acc[mt][nt], ah[mt], bl[nt]);
      if (AP == 2) {
        #pragma unroll
        for (int mt = 0; mt < 4; mt++)
          #pragma unroll
          for (int nt = 0; nt < 4; nt++) mma16816(acc[mt][nt], al[mt], bh[nt]);
      }
    }
    __syncthreads();
  }
  #undef ISSUE

  #pragma unroll
  for (int mt = 0; mt < 4; mt++) {
    int row = m0 + wm + mt * 16 + (lane >> 2);
    #pragma unroll
    for (int nt = 0; nt < 4; nt++) {
      int col = n0 + wn + nt * 8 + ((lane & 3) << 1);
      *(float2*)&C[(size_t)row * N + col] =
          make_float2(acc[mt][nt][0] * escale, acc[mt][nt][1] * escale);
      *(float2*)&C[(size_t)(row + 8) * N + col] =
          make_float2(acc[mt][nt][2] * escale, acc[mt][nt][3] * escale);
    }
  }
}

// ---------------- inv_freq table ----------------
__global__ void invf_init() {
  int i = threadIdx.x;
  if (i < 128)
    g_invf[i] = exp(((double)(-2.0 * i) / 256.0) * 9.210340371976184);
}

// ---------------- RoPE: fp32 (64x) qkv -> head-major fp16 ----------------
__global__ __launch_bounds__(256) void rope_kernel(const int* __restrict__ pos) {
  int idx = blockIdx.x * 256 + threadIdx.x;
  int i   = idx & 127;
  int hh  = (idx >> 7) & 31;
  int row = idx >> 12;
  int p = pos[row];
  double ang = (double)p * g_invf[i];
  const double INV2PI = 0.15915494309189535;
  const double TWOPI  = 6.283185307179586;
  int kk = __double2int_rn(ang * INV2PI);
  float fr = (float)(ang - TWOPI * (double)kk);
  float s, c;
  __sincosf(fr, &s, &c);
  const float* base = g_qkv + (size_t)row * cQKV + hh * cHD;
  const float inv64 = 1.0f / 64.0f;
  float x1 = base[i], x2 = base[i + 128];
  float y1 = (x1 * c - x2 * s) * inv64;
  float y2 = (x2 * c + x1 * s) * inv64;
  int b = row >> 11, sidx = row & 2047;
  bool isq = hh < 16;
  int head = isq ? hh : hh - 16;
  size_t o = ((size_t)(b * cNH + head) * cS + sidx) * cHD + i;
  if (isq) {
    y1 *= 0.0625f;   // fold softmax scale
    y2 *= 0.0625f;
    g_qh[o]       = __float2half(y1);
    g_qh[o + 128] = __float2half(y2);
  } else {
    __half h1 = __float2half(y1), h2 = __float2half(y2);
    g_kh[o]       = h1;
    g_kh[o + 128] = h2;
    g_kl[o]       = __float2half(y1 - __half2float(h1));
    g_kl[o + 128] = __float2half(y2 - __half2float(h2));
  }
}

// ---------------- V split: fp32 (64x) -> head-major fp16 hi/lo -----------
__global__ __launch_bounds__(256) void vsplit_kernel() {
  int idx = blockIdx.x * 256 + threadIdx.x;
  int d4 = idx & 63;
  int h  = (idx >> 6) & 15;
  int row = idx >> 10;
  int b = row >> 11, sidx = row & 2047;
  const float inv64 = 1.0f / 64.0f;
  float4 v = *(const float4*)(g_qkv + (size_t)row * cQKV + 2 * cQSZ + h * cHD +
                              d4 * 4);
  float vv[4] = {v.x * inv64, v.y * inv64, v.z * inv64, v.w * inv64};
  size_t o = ((size_t)(b * cNH + h) * cS + sidx) * cHD + d4 * 4;
  __half hh[4], ll[4];
  #pragma unroll
  for (int q = 0; q < 4; q++) {
    hh[q] = __float2half(vv[q]);
    ll[q] = __float2half(vv[q] - __half2float(hh[q]));
  }
  *(__half2*)(g_vh + o)     = __halves2half2(hh[0], hh[1]);
  *(__half2*)(g_vh + o + 2) = __halves2half2(hh[2], hh[3]);
  *(__half2*)(g_vl + o)     = __halves2half2(ll[0], ll[1]);
  *(__half2*)(g_vl + o + 2) = __halves2half2(ll[2], ll[3]);
}

// ---------------- HMMA flash attention (fp16, 2-pass QK and PV) ----------
constexpr int FQST = 264;
constexpr int FPST = 72;
constexpr int F_QH = 0;
constexpr int F_KH = 1 * 64 * FQST;
constexpr int F_KL = 2 * 64 * FQST;
constexpr int F_VH = 3 * 64 * FQST;
constexpr int F_VL = 4 * 64 * FQST;
constexpr int F_PH = 5 * 64 * FQST;
constexpr int F_TOT = F_PH + 64 * FPST;
constexpr int FLASH_SMEM = F_TOT * 2 + 448 * 4;

__global__ __launch_bounds__(256, 1) void flash_hmma(
    __half* __restrict__ ath, __half* __restrict__ atl) {
  extern __shared__ __half smem[];
  const uint32_t sb = smem_u32(smem);
  float* fre  = (float*)(smem + F_TOT);
  float* m_s  = fre;
  float* l_s  = fre + 64;
  float* f_s  = fre + 128;
  float* rmax = fre + 192;
  float* rsum = fre + 320;

  const int qtile = gridDim.x - 1 - blockIdx.x;
  const int bh = blockIdx.y;
  const int b = bh >> 4, h = bh & 15;
  const int tid = threadIdx.x, lane = tid & 31, wid = tid >> 5;
  const int wm = wid & 3, wg = wid >> 2;
  const int q0 = qtile * 64;

  const __half* qhb = g_qh + ((size_t)bh * cS + q0) * cHD;
  const __half* khb = g_kh + (size_t)bh * cS * cHD;
  const __half* klb = g_kl + (size_t)bh * cS * cHD;
  const __half* vhb = g_vh + (size_t)bh * cS * cHD;
  const __half* vlb = g_vl + (size_t)bh * cS * cHD;

  #define LOADP(gptr, soff)                                              \
    do {                                                                 \
      _Pragma("unroll")                                                  \
      for (int i_ = 0; i_ < 8; i_++) {                                   \
        int id_ = tid + 256 * i_;                                        \
        int r_ = id_ >> 5, c_ = id_ & 31;                                \
        CP_ASYNC16(sb + (uint32_t)((soff) + r_ * FQST + c_ * 8) * 2,     \
                   (gptr) + r_ * 256 + c_ * 8);                          \
      }                                                                  \
    } while (0)

  LOADP(qhb, F_QH);
  LOADP(khb, F_KH);
  LOADP(klb, F_KL);
  CP_COMMIT();
  LOADP(vhb, F_VH);
  LOADP(vlb, F_VL);
  CP_COMMIT();

  if (tid < 64) { m_s[tid] = -1e30f; l_s[tid] = 0.0f; }

  float o[16][4];
  #pragma unroll
  for (int i = 0; i < 16; i++)
    #pragma unroll
    for (int j = 0; j < 4; j++) o[i][j] = 0.0f;

  const uint32_t pQh = sb + F_QH * 2;
  const uint32_t pKh = sb + F_KH * 2, pKl = sb + F_KL * 2;
  const uint32_t pVh = sb + F_VH * 2, pVl = sb + F_VL * 2;
  const uint32_t pPh = sb + F_PH * 2;

  const int arow = 16 * wm + (lane & 15);
  const int acol = (lane >> 4) * 8;
  const int brow = wg * 32 + (lane & 7) + (lane >> 4) * 8;
  const int bcol = ((lane >> 3) & 1) * 8;
  const int row0 = 16 * wm + (lane >> 2);

  for (int jt = 0; jt <= qtile; jt++) {
    CP_WAIT(1);
    __syncthreads();

    // ---- S = Q K^T (Q single, K hi/lo: 2 passes) ----
    float s[4][4];
    #pragma unroll
    for (int nt = 0; nt < 4; nt++)
      #pragma unroll
      for (int c = 0; c < 4; c++) s[nt][c] = 0.0f;

    #pragma unroll 4
    for (int ks = 0; ks < 16; ks++) {
      const int k0 = ks * 16;
      uint32_t aoff = (uint32_t)(arow * FQST + k0 + acol) * 2;
      uint32_t aqh[4], bkh0[4], bkh1[4], bkl0[4], bkl1[4];
      LDSM4(aqh[0], aqh[1], aqh[2], aqh[3], pQh + aoff);
      uint32_t boff0 = (uint32_t)(brow * FQST + k0 + bcol) * 2;
      uint32_t boff1 = boff0 + 16 * FQST * 2;
      LDSM4(bkh0[0], bkh0[1], bkh0[2], bkh0[3], pKh + boff0);
      LDSM4(bkh1[0], bkh1[1], bkh1[2], bkh1[3], pKh + boff1);
      LDSM4(bkl0[0], bkl0[1], bkl0[2], bkl0[3], pKl + boff0);
      LDSM4(bkl1[0], bkl1[1], bkl1[2], bkl1[3], pKl + boff1);
      uint32_t* bhp[4] = {&bkh0[0], &bkh0[2], &bkh1[0], &bkh1[2]};
      uint32_t* blp[4] = {&bkl0[0], &bkl0[2], &bkl1[0], &bkl1[2]};
      #pragma unroll
      for (int nt = 0; nt < 4; nt++) mma16816(s[nt], aqh, bhp[nt]);
      #pragma unroll
      for (int nt = 0; nt < 4; nt++) mma16816(s[nt], aqh, blp[nt]);
    }

    // ---- causal mask ----
    if (jt == qtile) {
      #pragma unroll
      for (int nt = 0; nt < 4; nt++)
        #pragma unroll
        for (int c = 0; c < 4; c++) {
          int kvloc = wg * 32 + nt * 8 + (lane & 3) * 2 + (c & 1);
          int qloc = 16 * wm + (lane >> 2) + 8 * (c >> 1);
          if (kvloc > qloc) s[nt][c] = -1e30f;
        }
    }

    // ---- row max ----
    float lm0 = -1e30f, lm1 = -1e30f;
    #pragma unroll
    for (int nt = 0; nt < 4; nt++) {
      lm0 = fmaxf(lm0, fmaxf(s[nt][0], s[nt][1]));
      lm1 = fmaxf(lm1, fmaxf(s[nt][2], s[nt][3]));
    }
    lm0 = fmaxf(lm0, __shfl_xor_sync(0xffffffffu, lm0, 1));
    lm0 = fmaxf(lm0, __shfl_xor_sync(0xffffffffu, lm0, 2));
    lm1 = fmaxf(lm1, __shfl_xor_sync(0xffffffffu, lm1, 1));
    lm1 = fmaxf(lm1, __shfl_xor_sync(0xffffffffu, lm1, 2));
    if ((lane & 3) == 0) {
      rmax[wg * 64 + row0] = lm0;
      rmax[wg * 64 + row0 + 8] = lm1;
    }
    __syncthreads();
    if (tid < 64) {
      float mo = m_s[tid];
      float mn = fmaxf(mo, fmaxf(rmax[tid], rmax[64 + tid]));
      f_s[tid] = __expf(mo - mn);
      m_s[tid] = mn;
    }
    __syncthreads();

    // ---- exp, P store (single fp16), O rescale, row sums ----
    {
      float mn0 = m_s[row0], mn1 = m_s[row0 + 8];
      float sum0 = 0.0f, sum1 = 0.0f;
      #pragma unroll
      for (int nt = 0; nt < 4; nt++) {
        float p0 = __expf(s[nt][0] - mn0);
        float p1 = __expf(s[nt][1] - mn0);
        float p2 = __expf(s[nt][2] - mn1);
        float p3 = __expf(s[nt][3] - mn1);
        sum0 += p0 + p1;
        sum1 += p2 + p3;
        int col = wg * 32 + nt * 8 + (lane & 3) * 2;
        *(__half2*)(smem + F_PH + row0 * FPST + col) = mk_h2(p0, p1);
        *(__half2*)(smem + F_PH + (row0 + 8) * FPST + col) = mk_h2(p2, p3);
      }
      sum0 += __shfl_xor_sync(0xffffffffu, sum0, 1);
      sum0 += __shfl_xor_sync(0xffffffffu, sum0, 2);
      sum1 += __shfl_xor_sync(0xffffffffu, sum1, 1);
      sum1 += __shfl_xor_sync(0xffffffffu, sum1, 2);
      if ((lane & 3) == 0) {
        rsum[wg * 64 + row0] = sum0;
        rsum[wg * 64 + row0 + 8] = sum1;
      }
      float f0 = f_s[row0], f1 = f_s[row0 + 8];
      #pragma unroll
      for (int dt = 0; dt < 16; dt++) {
        o[dt][0] *= f0; o[dt][1] *= f0;
        o[dt][2] *= f1; o[dt][3] *= f1;
      }
    }

    CP_WAIT(0);
    __syncthreads();

    if (jt < qtile) {
      LOADP(khb + (jt + 1) * 64 * 256, F_KH);
      LOADP(klb + (jt + 1) * 64 * 256, F_KL);
      CP_COMMIT();
    }
    if (tid < 64) l_s[tid] = l_s[tid] * f_s[tid] + rsum[tid] + rsum[64 + tid];

    // ---- O += P V (P single, V hi/lo: 2 passes) ----
    #pragma unroll
    for (int ks = 0; ks < 4; ks++) {
      const int k0 = ks * 16;
      uint32_t aph[4];
      uint32_t paoff = (uint32_t)(arow * FPST + k0 + acol) * 2;
      LDSM4(aph[0], aph[1], aph[2], aph[3], pPh + paoff);
      const int vrow = k0 + (lane & 15);
      #pragma unroll
      for (int dt2 = 0; dt2 < 8; dt2++) {
        int dbase = wg * 128 + dt2 * 16 + (lane >> 4) * 8;
        uint32_t voff = (uint32_t)(vrow * FQST + dbase) * 2;
        uint32_t bvh[4], bvl[4];
        LDSM4T(bvh[0], bvh[1], bvh[2], bvh[3], pVh + voff);
        LDSM4T(bvl[0], bvl[1], bvl[2], bvl[3], pVl + voff);
        mma16816(o[dt2 * 2], aph, &bvh[0]);
        mma16816(o[dt2 * 2], aph, &bvl[0]);
        mma16816(o[dt2 * 2 + 1], aph, &bvh[2]);
        mma16816(o[dt2 * 2 + 1], aph, &bvl[2]);
      }
    }
    __syncthreads();
    if (jt < qtile) {
      LOADP(vhb + (jt + 1) * 64 * 256, F_VH);
      LOADP(vlb + (jt + 1) * 64 * 256, F_VL);
      CP_COMMIT();
    }
  }
  #undef LOADP

  // ---- epilogue ----
  float rl0 = 1.0f / l_s[row0];
  float rl1 = 1.0f / l_s[row0 + 8];
  size_t g0 = ((size_t)(b * cS + q0 + row0)) * cQSZ + h * cHD;
  size_t g1 = g0 + 8 * cQSZ;
  #pragma unroll
  for (int dt = 0; dt < 16; dt++) {
    int col = wg * 128 + dt * 8 + (lane & 3) * 2;
    float v0 = o[dt][0] * rl0, v1 = o[dt][1] * rl0;
    float v2 = o[dt][2] * rl1, v3 = o[dt][3] * rl1;
    __half h0 = __float2half(v0), h1 = __float2half(v1);
    __half h2 = __float2half(v2), h3 = __float2half(v3);
    *(__half2*)(ath + g0 + col) = __halves2half2(h0, h1);
    *(__half2*)(ath + g1 + col) = __halves2half2(h2, h3);
    *(__half2*)(atl + g0 + col) =
        mk_h2(v0 - __half2float(h0), v1 - __half2float(h1));
    *(__half2*)(atl + g1 + col) =
        mk_h2(v2 - __half2float(h2), v3 - __half2float(h3));
  }
}

// ---------------- launch ----------------
extern "C" void kernel_launch(void* const* d_in, const int* in_sizes, int n_in,
                              void* d_out, int out_size) {
  (void)in_sizes; (void)n_in; (void)out_size;
  const float* hidden = (const float*)d_in[0];
  const int*   pos    = (const int*)d_in[1];
  const float* Wqkv   = (const float*)d_in[2];
  const float* Wo     = (const float*)d_in[3];
  float* out = (float*)d_out;

  float* qkv_p;
  __half *hidh, *w1h, *w1l, *ath, *atl, *w2h, *w2l;
  cudaGetSymbolAddress((void**)&qkv_p, g_qkv);
  cudaGetSymbolAddress((void**)&hidh, g_hid_h);
  cudaGetSymbolAddress((void**)&w1h, g_w1_h);
  cudaGetSymbolAddress((void**)&w1l, g_w1_l);
  cudaGetSymbolAddress((void**)&ath, g_at_h);
  cudaGetSymbolAddress((void**)&atl, g_at_l);
  cudaGetSymbolAddress((void**)&w2h, g_w2_h);
  cudaGetSymbolAddress((void**)&w2l, g_w2_l);

  constexpr int SM1 = 2 * 3 * PARTE * 2;   // AP=1: 61440
  constexpr int SM2 = 2 * 4 * PARTE * 2;   // AP=2: 81920
  cudaFuncSetAttribute(gemm_hmma<1>,
                       cudaFuncAttributeMaxDynamicSharedMemorySize, SM1);
  cudaFuncSetAttribute(gemm_hmma<2>,
                       cudaFuncAttributeMaxDynamicSharedMemorySize, SM2);
  cudaFuncSetAttribute(flash_hmma,
                       cudaFuncAttributeMaxDynamicSharedMemorySize, FLASH_SMEM);

  invf_init<<<1, 128>>>();
  {
    int n4 = cM * cH / 4;
    conv_kernel<<<(n4 + 255) / 256, 256>>>(hidden, hidh, n4);
    tsplit_kernel<<<dim3(cQKV / 32, cH / 32), 256>>>(Wqkv, w1h, w1l, cH, cQKV);
    tsplit_kernel<<<dim3(cH / 32, cQSZ / 32), 256>>>(Wo, w2h, w2l, cQSZ, cH);
  }
  // QKV projection: 2-pass (A single). C = 64 * qkv.
  gemm_hmma<1><<<dim3(cQKV / BN, cM / BM), 256, SM1>>>(
      hidh, hidh, w1h, w1l, qkv_p, cM, cQKV, cH, 1.0f);
  rope_kernel<<<(cM * 32 * 128) / 256, 256>>>(pos);
  vsplit_kernel<<<(cM * cQSZ / 4) / 256, 256>>>();
  flash_hmma<<<dim3(cS / 64, cB * cNH), 256, FLASH_SMEM>>>(ath, atl);
  // output projection: 3-pass (A hi/lo). C = 64 * out -> scale back.
  gemm_hmma<2><<<dim3(cH / BN, cM / BM), 256, SM2>>>(
      ath, atl, w2h, w2l, out, cM, cH, cQSZ, 1.0f / 64.0f);
}

// round 6
// speedup vs baseline: 1.9100x; 1.9100x over previous
#include <cuda_runtime.h>
#include <cuda_fp16.h>
#include <math.h>
#include <stdint.h>

// ---------------- problem constants ----------------
namespace {
constexpr int cB  = 2;
constexpr int cS  = 2048;
constexpr int cH  = 3072;
constexpr int cNH = 16;
constexpr int cHD = 256;
constexpr int cQSZ  = cNH * cHD;            // 4096
constexpr int cQKV  = 3 * cQSZ;             // 12288
constexpr int cM    = cB * cS;              // 4096 rows
}

// ---------------- scratch ----------------
__device__ float g_qkv[(size_t)cM * cQKV];          // fp32, = 64 * true qkv
__device__ __half g_hid_h[(size_t)cM * cH];         // hidden fp16 (single)
__device__ __half g_w1_h[(size_t)cQKV * cH];        // (64*Wqkv)^T hi only
__device__ __half g_w1_l[(size_t)cQKV * cH];        // unused (kept for ptr)
__device__ __half g_at_h[(size_t)cM * cQSZ];        // attn out hi
__device__ __half g_at_l[(size_t)cM * cQSZ];
__device__ __half g_w2_h[(size_t)cH * cQSZ];        // (64*Wo)^T hi
__device__ __half g_w2_l[(size_t)cH * cQSZ];
// head-major [bh][s][d]
__device__ __half g_qh[(size_t)cM * cQSZ];          // Q single (scaled)
__device__ __half g_kh[(size_t)cM * cQSZ];
__device__ __half g_kl[(size_t)cM * cQSZ];
__device__ __half g_vh[(size_t)cM * cQSZ];
__device__ __half g_vl[(size_t)cM * cQSZ];
__device__ double g_invf[128];

// ---------------- helpers (base ISA, compute_103-safe) ----------------
__device__ __forceinline__ uint32_t smem_u32(const void* p) {
  uint32_t a;
  asm("{ .reg .u64 t; cvta.to.shared.u64 t, %1; cvt.u32.u64 %0, t; }"
      : "=r"(a) : "l"(p));
  return a;
}
#define CP_ASYNC16(dst, src) \
  asm volatile("cp.async.cg.shared.global [%0], [%1], 16;" :: "r"(dst), "l"(src))
#define CP_COMMIT() asm volatile("cp.async.commit_group;" ::: "memory")
#define CP_WAIT(n)  asm volatile("cp.async.wait_group %0;" :: "n"(n) : "memory")
#define LDSM4(r0, r1, r2, r3, addr) \
  asm volatile("ldmatrix.sync.aligned.m8n8.x4.shared.b16 {%0,%1,%2,%3}, [%4];" \
               : "=r"(r0), "=r"(r1), "=r"(r2), "=r"(r3) : "r"(addr))
#define LDSM4T(r0, r1, r2, r3, addr) \
  asm volatile("ldmatrix.sync.aligned.m8n8.x4.trans.shared.b16 {%0,%1,%2,%3}, [%4];" \
               : "=r"(r0), "=r"(r1), "=r"(r2), "=r"(r3) : "r"(addr))

__device__ __forceinline__ void mma16816(float* d, const uint32_t* a,
                                         const uint32_t* b) {
  asm volatile(
      "mma.sync.aligned.m16n8k16.row.col.f32.f16.f16.f32 "
      "{%0,%1,%2,%3}, {%4,%5,%6,%7}, {%8,%9}, {%0,%1,%2,%3};"
      : "+f"(d[0]), "+f"(d[1]), "+f"(d[2]), "+f"(d[3])
      : "r"(a[0]), "r"(a[1]), "r"(a[2]), "r"(a[3]), "r"(b[0]), "r"(b[1]));
}

__device__ __forceinline__ __half2 mk_h2(float a, float b) {
  return __halves2half2(__float2half(a), __float2half(b));
}

// ---------------- hidden fp32 -> fp16 single ----------------
__global__ __launch_bounds__(256) void conv_kernel(
    const float* __restrict__ x, __half* __restrict__ h, int n4) {
  int i = blockIdx.x * 256 + threadIdx.x;
  if (i >= n4) return;
  float4 v = ((const float4*)x)[i];
  ((__half2*)h)[2 * i]     = mk_h2(v.x, v.y);
  ((__half2*)h)[2 * i + 1] = mk_h2(v.z, v.w);
}

// ---------------- transpose + scale(64) + split hi(/lo) ------------------
template <bool WLO>
__global__ __launch_bounds__(256) void tsplit_kernel(
    const float* __restrict__ W, __half* __restrict__ Th,
    __half* __restrict__ Tl, int K, int N) {
  __shared__ float sm[32][33];
  int n0 = blockIdx.x * 32, k0 = blockIdx.y * 32;
  int tx = threadIdx.x & 31, ty = threadIdx.x >> 5;
  #pragma unroll
  for (int q = 0; q < 4; q++)
    sm[ty + 8 * q][tx] = W[(size_t)(k0 + ty + 8 * q) * N + n0 + tx];
  __syncthreads();
  #pragma unroll
  for (int q = 0; q < 4; q++) {
    float x = sm[tx][ty + 8 * q] * 64.0f;
    __half h = __float2half(x);
    size_t o = (size_t)(n0 + ty + 8 * q) * K + k0 + tx;
    Th[o] = h;
    if (WLO) Tl[o] = __float2half(x - __half2float(h));
  }
}

// ---------------- HMMA GEMM: C = escale * A[M,K] * Bt[N,K]^T --------------
// Passes: Ah*Bh always; +Ah*Bl if BP==2; +Al*Bh if AP==2.
constexpr int BM = 128, BN = 128, BKt = 32;
constexpr int AST = 40;
constexpr int PARTE = 128 * AST;

template <int AP, int BP>
__global__ __launch_bounds__(256, 2) void gemm_hmma(
    const __half* __restrict__ Ah, const __half* __restrict__ Al,
    const __half* __restrict__ Bh, const __half* __restrict__ Bl,
    float* __restrict__ C, int M, int N, int K, float escale) {
  constexpr int PARTS = AP + BP;
  constexpr int BUFB = PARTS * PARTE * 2;   // bytes per stage
  extern __shared__ __half smb[];
  const uint32_t sbase = smem_u32(smb);
  const int tid = threadIdx.x, lane = tid & 31, wid = tid >> 5;
  const int m0 = blockIdx.y * BM, n0 = blockIdx.x * BN;
  const int wm = (wid & 1) * 64, wn = (wid >> 1) * 32;

  float acc[4][4][4];
  #pragma unroll
  for (int i = 0; i < 4; i++)
    #pragma unroll
    for (int j = 0; j < 4; j++)
      #pragma unroll
      for (int q = 0; q < 4; q++) acc[i][j][q] = 0.0f;

  const int T = K / BKt;
  int ldr[2], ldc[2];
  #pragma unroll
  for (int i = 0; i < 2; i++) {
    int idx = tid + i * 256;
    ldr[i] = idx >> 2;
    ldc[i] = idx & 3;
  }

  #define ISSUE(t)                                                          \
    do {                                                                    \
      int k0_ = (t) * BKt;                                                  \
      uint32_t db_ = sbase + ((t) & 1) * BUFB;                              \
      _Pragma("unroll")                                                     \
      for (int i_ = 0; i_ < 2; i_++) {                                      \
        int r_ = ldr[i_], c_ = ldc[i_];                                     \
        size_t ao_ = (size_t)(m0 + r_) * K + k0_ + c_ * 8;                  \
        size_t bo_ = (size_t)(n0 + r_) * K + k0_ + c_ * 8;                  \
        uint32_t d_ = db_ + (r_ * AST + c_ * 8) * 2;                        \
        CP_ASYNC16(d_, Ah + ao_);                                           \
        if (AP == 2) CP_ASYNC16(d_ + PARTE * 2, Al + ao_);                  \
        CP_ASYNC16(d_ + AP * PARTE * 2, Bh + bo_);                          \
        if (BP == 2) CP_ASYNC16(d_ + (AP + 1) * PARTE * 2, Bl + bo_);       \
      }                                                                     \
    } while (0)

  ISSUE(0);
  CP_COMMIT();

  for (int t = 0; t < T; t++) {
    if (t + 1 < T) {
      ISSUE(t + 1);
      CP_COMMIT();
      CP_WAIT(1);
    } else {
      CP_WAIT(0);
    }
    __syncthreads();

    uint32_t base = sbase + (t & 1) * BUFB;
    const uint32_t pAh = base;
    const uint32_t pAl = base + PARTE * 2;
    const uint32_t pBh = base + AP * PARTE * 2;
    const uint32_t pBl = pBh + PARTE * 2;

    #pragma unroll
    for (int ks = 0; ks < 2; ks++) {
      const int kb = ks * 16;
      uint32_t ah[4][4], al[4][4], bh[4][2], bl[4][2];
      #pragma unroll
      for (int mt = 0; mt < 4; mt++) {
        int r = wm + mt * 16 + (lane & 15);
        int c = kb + ((lane >> 4) << 3);
        uint32_t off = (uint32_t)(r * AST + c) * 2;
        LDSM4(ah[mt][0], ah[mt][1], ah[mt][2], ah[mt][3], pAh + off);
        if (AP == 2)
          LDSM4(al[mt][0], al[mt][1], al[mt][2], al[mt][3], pAl + off);
      }
      #pragma unroll
      for (int p = 0; p < 2; p++) {
        int g = lane >> 3;
        int r = wn + (p * 2 + (g >> 1)) * 8 + (lane & 7);
        int c = kb + ((g & 1) << 3);
        uint32_t off = (uint32_t)(r * AST + c) * 2;
        LDSM4(bh[2 * p][0], bh[2 * p][1], bh[2 * p + 1][0], bh[2 * p + 1][1],
              pBh + off);
        if (BP == 2)
          LDSM4(bl[2 * p][0], bl[2 * p][1], bl[2 * p + 1][0], bl[2 * p + 1][1],
                pBl + off);
      }
      #pragma unroll
      for (int mt = 0; mt < 4; mt++)
        #pragma unroll
        for (int nt = 0; nt < 4; nt++) mma16816(acc[mt][nt], ah[mt], bh[nt]);
      if (BP == 2) {
        #pragma unroll
        for (int mt = 0; mt < 4; mt++)
          #pragma unroll
          for (int nt = 0; nt < 4; nt++) mma16816(acc[mt][nt], ah[mt], bl[nt]);
      }
      if (AP == 2) {
        #pragma unroll
        for (int mt = 0; mt < 4; mt++)
          #pragma unroll
          for (int nt = 0; nt < 4; nt++) mma16816(acc[mt][nt], al[mt], bh[nt]);
      }
    }
    __syncthreads();
  }
  #undef ISSUE

  #pragma unroll
  for (int mt = 0; mt < 4; mt++) {
    int row = m0 + wm + mt * 16 + (lane >> 2);
    #pragma unroll
    for (int nt = 0; nt < 4; nt++) {
      int col = n0 + wn + nt * 8 + ((lane & 3) << 1);
      *(float2*)&C[(size_t)row * N + col] =
          make_float2(acc[mt][nt][0] * escale, acc[mt][nt][1] * escale);
      *(float2*)&C[(size_t)(row + 8) * N + col] =
          make_float2(acc[mt][nt][2] * escale, acc[mt][nt][3] * escale);
    }
  }
}

// ---------------- inv_freq table ----------------
__global__ void invf_init() {
  int i = threadIdx.x;
  if (i < 128)
    g_invf[i] = exp(((double)(-2.0 * i) / 256.0) * 9.210340371976184);
}

// ---------------- RoPE: fp32 (64x) qkv -> head-major fp16 ----------------
__global__ __launch_bounds__(256) void rope_kernel(const int* __restrict__ pos) {
  int idx = blockIdx.x * 256 + threadIdx.x;
  int i   = idx & 127;
  int hh  = (idx >> 7) & 31;
  int row = idx >> 12;
  int p = pos[row];
  double ang = (double)p * g_invf[i];
  const double INV2PI = 0.15915494309189535;
  const double TWOPI  = 6.283185307179586;
  int kk = __double2int_rn(ang * INV2PI);
  float fr = (float)(ang - TWOPI * (double)kk);
  float s, c;
  __sincosf(fr, &s, &c);
  const float* base = g_qkv + (size_t)row * cQKV + hh * cHD;
  const float inv64 = 1.0f / 64.0f;
  float x1 = base[i], x2 = base[i + 128];
  float y1 = (x1 * c - x2 * s) * inv64;
  float y2 = (x2 * c + x1 * s) * inv64;
  int b = row >> 11, sidx = row & 2047;
  bool isq = hh < 16;
  int head = isq ? hh : hh - 16;
  size_t o = ((size_t)(b * cNH + head) * cS + sidx) * cHD + i;
  if (isq) {
    y1 *= 0.0625f;   // fold softmax scale
    y2 *= 0.0625f;
    g_qh[o]       = __float2half(y1);
    g_qh[o + 128] = __float2half(y2);
  } else {
    __half h1 = __float2half(y1), h2 = __float2half(y2);
    g_kh[o]       = h1;
    g_kh[o + 128] = h2;
    g_kl[o]       = __float2half(y1 - __half2float(h1));
    g_kl[o + 128] = __float2half(y2 - __half2float(h2));
  }
}

// ---------------- V split: fp32 (64x) -> head-major fp16 hi/lo -----------
__global__ __launch_bounds__(256) void vsplit_kernel() {
  int idx = blockIdx.x * 256 + threadIdx.x;
  int d4 = idx & 63;
  int h  = (idx >> 6) & 15;
  int row = idx >> 10;
  int b = row >> 11, sidx = row & 2047;
  const float inv64 = 1.0f / 64.0f;
  float4 v = *(const float4*)(g_qkv + (size_t)row * cQKV + 2 * cQSZ + h * cHD +
                              d4 * 4);
  float vv[4] = {v.x * inv64, v.y * inv64, v.z * inv64, v.w * inv64};
  size_t o = ((size_t)(b * cNH + h) * cS + sidx) * cHD + d4 * 4;
  __half hh[4], ll[4];
  #pragma unroll
  for (int q = 0; q < 4; q++) {
    hh[q] = __float2half(vv[q]);
    ll[q] = __float2half(vv[q] - __half2float(hh[q]));
  }
  *(__half2*)(g_vh + o)     = __halves2half2(hh[0], hh[1]);
  *(__half2*)(g_vh + o + 2) = __halves2half2(hh[2], hh[3]);
  *(__half2*)(g_vl + o)     = __halves2half2(ll[0], ll[1]);
  *(__half2*)(g_vl + o + 2) = __halves2half2(ll[2], ll[3]);
}

// ---------------- HMMA flash attention (fp16, 2-pass QK and PV) ----------
constexpr int FQST = 264;
constexpr int FPST = 72;
constexpr int F_QH = 0;
constexpr int F_KH = 1 * 64 * FQST;
constexpr int F_KL = 2 * 64 * FQST;
constexpr int F_VH = 3 * 64 * FQST;
constexpr int F_VL = 4 * 64 * FQST;
constexpr int F_PH = 5 * 64 * FQST;
constexpr int F_TOT = F_PH + 64 * FPST;
constexpr int FLASH_SMEM = F_TOT * 2 + 448 * 4;

__global__ __launch_bounds__(256, 1) void flash_hmma(
    __half* __restrict__ ath, __half* __restrict__ atl) {
  extern __shared__ __half smem[];
  const uint32_t sb = smem_u32(smem);
  float* fre  = (float*)(smem + F_TOT);
  float* m_s  = fre;
  float* l_s  = fre + 64;
  float* f_s  = fre + 128;
  float* rmax = fre + 192;
  float* rsum = fre + 320;

  const int qtile = gridDim.x - 1 - blockIdx.x;
  const int bh = blockIdx.y;
  const int b = bh >> 4, h = bh & 15;
  const int tid = threadIdx.x, lane = tid & 31, wid = tid >> 5;
  const int wm = wid & 3, wg = wid >> 2;
  const int q0 = qtile * 64;

  const __half* qhb = g_qh + ((size_t)bh * cS + q0) * cHD;
  const __half* khb = g_kh + (size_t)bh * cS * cHD;
  const __half* klb = g_kl + (size_t)bh * cS * cHD;
  const __half* vhb = g_vh + (size_t)bh * cS * cHD;
  const __half* vlb = g_vl + (size_t)bh * cS * cHD;

  #define LOADP(gptr, soff)                                              \
    do {                                                                 \
      _Pragma("unroll")                                                  \
      for (int i_ = 0; i_ < 8; i_++) {                                   \
        int id_ = tid + 256 * i_;                                        \
        int r_ = id_ >> 5, c_ = id_ & 31;                                \
        CP_ASYNC16(sb + (uint32_t)((soff) + r_ * FQST + c_ * 8) * 2,     \
                   (gptr) + r_ * 256 + c_ * 8);                          \
      }                                                                  \
    } while (0)

  LOADP(qhb, F_QH);
  LOADP(khb, F_KH);
  LOADP(klb, F_KL);
  CP_COMMIT();
  LOADP(vhb, F_VH);
  LOADP(vlb, F_VL);
  CP_COMMIT();

  if (tid < 64) { m_s[tid] = -1e30f; l_s[tid] = 0.0f; }

  float o[16][4];
  #pragma unroll
  for (int i = 0; i < 16; i++)
    #pragma unroll
    for (int j = 0; j < 4; j++) o[i][j] = 0.0f;

  const uint32_t pQh = sb + F_QH * 2;
  const uint32_t pKh = sb + F_KH * 2, pKl = sb + F_KL * 2;
  const uint32_t pVh = sb + F_VH * 2, pVl = sb + F_VL * 2;
  const uint32_t pPh = sb + F_PH * 2;

  const int arow = 16 * wm + (lane & 15);
  const int acol = (lane >> 4) * 8;
  const int brow = wg * 32 + (lane & 7) + (lane >> 4) * 8;
  const int bcol = ((lane >> 3) & 1) * 8;
  const int row0 = 16 * wm + (lane >> 2);

  for (int jt = 0; jt <= qtile; jt++) {
    CP_WAIT(1);
    __syncthreads();

    // ---- S = Q K^T (Q single, K hi/lo: 2 passes) ----
    float s[4][4];
    #pragma unroll
    for (int nt = 0; nt < 4; nt++)
      #pragma unroll
      for (int c = 0; c < 4; c++) s[nt][c] = 0.0f;

    #pragma unroll 4
    for (int ks = 0; ks < 16; ks++) {
      const int k0 = ks * 16;
      uint32_t aoff = (uint32_t)(arow * FQST + k0 + acol) * 2;
      uint32_t aqh[4], bkh0[4], bkh1[4], bkl0[4], bkl1[4];
      LDSM4(aqh[0], aqh[1], aqh[2], aqh[3], pQh + aoff);
      uint32_t boff0 = (uint32_t)(brow * FQST + k0 + bcol) * 2;
      uint32_t boff1 = boff0 + 16 * FQST * 2;
      LDSM4(bkh0[0], bkh0[1], bkh0[2], bkh0[3], pKh + boff0);
      LDSM4(bkh1[0], bkh1[1], bkh1[2], bkh1[3], pKh + boff1);
      LDSM4(bkl0[0], bkl0[1], bkl0[2], bkl0[3], pKl + boff0);
      LDSM4(bkl1[0], bkl1[1], bkl1[2], bkl1[3], pKl + boff1);
      uint32_t* bhp[4] = {&bkh0[0], &bkh0[2], &bkh1[0], &bkh1[2]};
      uint32_t* blp[4] = {&bkl0[0], &bkl0[2], &bkl1[0], &bkl1[2]};
      #pragma unroll
      for (int nt = 0; nt < 4; nt++) mma16816(s[nt], aqh, bhp[nt]);
      #pragma unroll
      for (int nt = 0; nt < 4; nt++) mma16816(s[nt], aqh, blp[nt]);
    }

    // ---- causal mask ----
    if (jt == qtile) {
      #pragma unroll
      for (int nt = 0; nt < 4; nt++)
        #pragma unroll
        for (int c = 0; c < 4; c++) {
          int kvloc = wg * 32 + nt * 8 + (lane & 3) * 2 + (c & 1);
          int qloc = 16 * wm + (lane >> 2) + 8 * (c >> 1);
          if (kvloc > qloc) s[nt][c] = -1e30f;
        }
    }

    // ---- row max ----
    float lm0 = -1e30f, lm1 = -1e30f;
    #pragma unroll
    for (int nt = 0; nt < 4; nt++) {
      lm0 = fmaxf(lm0, fmaxf(s[nt][0], s[nt][1]));
      lm1 = fmaxf(lm1, fmaxf(s[nt][2], s[nt][3]));
    }
    lm0 = fmaxf(lm0, __shfl_xor_sync(0xffffffffu, lm0, 1));
    lm0 = fmaxf(lm0, __shfl_xor_sync(0xffffffffu, lm0, 2));
    lm1 = fmaxf(lm1, __shfl_xor_sync(0xffffffffu, lm1, 1));
    lm1 = fmaxf(lm1, __shfl_xor_sync(0xffffffffu, lm1, 2));
    if ((lane & 3) == 0) {
      rmax[wg * 64 + row0] = lm0;
      rmax[wg * 64 + row0 + 8] = lm1;
    }
    __syncthreads();
    if (tid < 64) {
      float mo = m_s[tid];
      float mn = fmaxf(mo, fmaxf(rmax[tid], rmax[64 + tid]));
      f_s[tid] = __expf(mo - mn);
      m_s[tid] = mn;
    }
    __syncthreads();

    // ---- exp, P store (single fp16), O rescale, row sums ----
    {
      float mn0 = m_s[row0], mn1 = m_s[row0 + 8];
      float sum0 = 0.0f, sum1 = 0.0f;
      #pragma unroll
      for (int nt = 0; nt < 4; nt++) {
        float p0 = __expf(s[nt][0] - mn0);
        float p1 = __expf(s[nt][1] - mn0);
        float p2 = __expf(s[nt][2] - mn1);
        float p3 = __expf(s[nt][3] - mn1);
        sum0 += p0 + p1;
        sum1 += p2 + p3;
        int col = wg * 32 + nt * 8 + (lane & 3) * 2;
        *(__half2*)(smem + F_PH + row0 * FPST + col) = mk_h2(p0, p1);
        *(__half2*)(smem + F_PH + (row0 + 8) * FPST + col) = mk_h2(p2, p3);
      }
      sum0 += __shfl_xor_sync(0xffffffffu, sum0, 1);
      sum0 += __shfl_xor_sync(0xffffffffu, sum0, 2);
      sum1 += __shfl_xor_sync(0xffffffffu, sum1, 1);
      sum1 += __shfl_xor_sync(0xffffffffu, sum1, 2);
      if ((lane & 3) == 0) {
        rsum[wg * 64 + row0] = sum0;
        rsum[wg * 64 + row0 + 8] = sum1;
      }
      float f0 = f_s[row0], f1 = f_s[row0 + 8];
      #pragma unroll
      for (int dt = 0; dt < 16; dt++) {
        o[dt][0] *= f0; o[dt][1] *= f0;
        o[dt][2] *= f1; o[dt][3] *= f1;
      }
    }

    CP_WAIT(0);
    __syncthreads();

    if (jt < qtile) {
      LOADP(khb + (jt + 1) * 64 * 256, F_KH);
      LOADP(klb + (jt + 1) * 64 * 256, F_KL);
      CP_COMMIT();
    }
    if (tid < 64) l_s[tid] = l_s[tid] * f_s[tid] + rsum[tid] + rsum[64 + tid];

    // ---- O += P V (P single, V hi/lo: 2 passes) ----
    #pragma unroll
    for (int ks = 0; ks < 4; ks++) {
      const int k0 = ks * 16;
      uint32_t aph[4];
      uint32_t paoff = (uint32_t)(arow * FPST + k0 + acol) * 2;
      LDSM4(aph[0], aph[1], aph[2], aph[3], pPh + paoff);
      const int vrow = k0 + (lane & 15);
      #pragma unroll
      for (int dt2 = 0; dt2 < 8; dt2++) {
        int dbase = wg * 128 + dt2 * 16 + (lane >> 4) * 8;
        uint32_t voff = (uint32_t)(vrow * FQST + dbase) * 2;
        uint32_t bvh[4], bvl[4];
        LDSM4T(bvh[0], bvh[1], bvh[2], bvh[3], pVh + voff);
        LDSM4T(bvl[0], bvl[1], bvl[2], bvl[3], pVl + voff);
        mma16816(o[dt2 * 2], aph, &bvh[0]);
        mma16816(o[dt2 * 2], aph, &bvl[0]);
        mma16816(o[dt2 * 2 + 1], aph, &bvh[2]);
        mma16816(o[dt2 * 2 + 1], aph, &bvl[2]);
      }
    }
    __syncthreads();
    if (jt < qtile) {
      LOADP(vhb + (jt + 1) * 64 * 256, F_VH);
      LOADP(vlb + (jt + 1) * 64 * 256, F_VL);
      CP_COMMIT();
    }
  }
  #undef LOADP

  // ---- epilogue ----
  float rl0 = 1.0f / l_s[row0];
  float rl1 = 1.0f / l_s[row0 + 8];
  size_t g0 = ((size_t)(b * cS + q0 + row0)) * cQSZ + h * cHD;
  size_t g1 = g0 + 8 * cQSZ;
  #pragma unroll
  for (int dt = 0; dt < 16; dt++) {
    int col = wg * 128 + dt * 8 + (lane & 3) * 2;
    float v0 = o[dt][0] * rl0, v1 = o[dt][1] * rl0;
    float v2 = o[dt][2] * rl1, v3 = o[dt][3] * rl1;
    __half h0 = __float2half(v0), h1 = __float2half(v1);
    __half h2 = __float2half(v2), h3 = __float2half(v3);
    *(__half2*)(ath + g0 + col) = __halves2half2(h0, h1);
    *(__half2*)(ath + g1 + col) = __halves2half2(h2, h3);
    *(__half2*)(atl + g0 + col) =
        mk_h2(v0 - __half2float(h0), v1 - __half2float(h1));
    *(__half2*)(atl + g1 + col) =
        mk_h2(v2 - __half2float(h2), v3 - __half2float(h3));
  }
}

// ---------------- launch ----------------
extern "C" void kernel_launch(void* const* d_in, const int* in_sizes, int n_in,
                              void* d_out, int out_size) {
  (void)in_sizes; (void)n_in; (void)out_size;
  const float* hidden = (const float*)d_in[0];
  const int*   pos    = (const int*)d_in[1];
  const float* Wqkv   = (const float*)d_in[2];
  const float* Wo     = (const float*)d_in[3];
  float* out = (float*)d_out;

  float* qkv_p;
  __half *hidh, *w1h, *w1l, *ath, *atl, *w2h, *w2l;
  cudaGetSymbolAddress((void**)&qkv_p, g_qkv);
  cudaGetSymbolAddress((void**)&hidh, g_hid_h);
  cudaGetSymbolAddress((void**)&w1h, g_w1_h);
  cudaGetSymbolAddress((void**)&w1l, g_w1_l);
  cudaGetSymbolAddress((void**)&ath, g_at_h);
  cudaGetSymbolAddress((void**)&atl, g_at_l);
  cudaGetSymbolAddress((void**)&w2h, g_w2_h);
  cudaGetSymbolAddress((void**)&w2l, g_w2_l);

  constexpr int SM11 = 2 * 2 * PARTE * 2;   // 40960
  constexpr int SM22 = 2 * 4 * PARTE * 2;   // 81920
  cudaFuncSetAttribute(gemm_hmma<1, 1>,
                       cudaFuncAttributeMaxDynamicSharedMemorySize, SM11);
  cudaFuncSetAttribute(gemm_hmma<2, 2>,
                       cudaFuncAttributeMaxDynamicSharedMemorySize, SM22);
  cudaFuncSetAttribute(flash_hmma,
                       cudaFuncAttributeMaxDynamicSharedMemorySize, FLASH_SMEM);

  invf_init<<<1, 128>>>();
  {
    int n4 = cM * cH / 4;
    conv_kernel<<<(n4 + 255) / 256, 256>>>(hidden, hidh, n4);
    tsplit_kernel<false><<<dim3(cQKV / 32, cH / 32), 256>>>(Wqkv, w1h, w1l,
                                                            cH, cQKV);
    tsplit_kernel<true><<<dim3(cH / 32, cQSZ / 32), 256>>>(Wo, w2h, w2l,
                                                           cQSZ, cH);
  }
  // QKV projection: 1 pass (A single, B single). C = 64 * qkv.
  gemm_hmma<1, 1><<<dim3(cQKV / BN, cM / BM), 256, SM11>>>(
      hidh, hidh, w1h, w1h, qkv_p, cM, cQKV, cH, 1.0f);
  rope_kernel<<<(cM * 32 * 128) / 256, 256>>>(pos);
  vsplit_kernel<<<(cM * cQSZ / 4) / 256, 256>>>();
  flash_hmma<<<dim3(cS / 64, cB * cNH), 256, FLASH_SMEM>>>(ath, atl);
  // output projection: 3 passes (A hi/lo, B hi/lo). C = 64 * out -> /64.
  gemm_hmma<2, 2><<<dim3(cH / BN, cM / BM), 256, SM22>>>(
      ath, atl, w2h, w2l, out, cM, cH, cQSZ, 1.0f / 64.0f);
}

// round 7
// speedup vs baseline: 2.7244x; 1.4264x over previous
#include <cuda_runtime.h>
#include <cuda_fp16.h>
#include <math.h>
#include <stdint.h>

// ---------------- problem constants ----------------
namespace {
constexpr int cB  = 2;
constexpr int cS  = 2048;
constexpr int cH  = 3072;
constexpr int cNH = 16;
constexpr int cHD = 256;
constexpr int cQSZ  = cNH * cHD;            // 4096
constexpr int cQKV  = 3 * cQSZ;             // 12288
constexpr int cM    = cB * cS;              // 4096 rows
}

// ---------------- scratch ----------------
__device__ float g_qkv[(size_t)cM * cQKV];          // fp32, = 64 * true qkv
__device__ __half g_hid_h[(size_t)cM * cH];         // hidden fp16
__device__ __half g_w1_h[(size_t)cQKV * cH];        // (64*Wqkv)^T fp16
__device__ __half g_at_h[(size_t)cM * cQSZ];        // attn out fp16
__device__ __half g_w2_h[(size_t)cH * cQSZ];        // (64*Wo)^T fp16
// head-major [bh][s][d] fp16 singles
__device__ __half g_qh[(size_t)cM * cQSZ];          // Q (softmax scale folded)
__device__ __half g_kh[(size_t)cM * cQSZ];
__device__ __half g_vh[(size_t)cM * cQSZ];
__device__ double g_invf[128];

// ---------------- helpers (base ISA, compute_103-safe) ----------------
__device__ __forceinline__ uint32_t smem_u32(const void* p) {
  uint32_t a;
  asm("{ .reg .u64 t; cvta.to.shared.u64 t, %1; cvt.u32.u64 %0, t; }"
      : "=r"(a) : "l"(p));
  return a;
}
#define CP_ASYNC16(dst, src) \
  asm volatile("cp.async.cg.shared.global [%0], [%1], 16;" :: "r"(dst), "l"(src))
#define CP_COMMIT() asm volatile("cp.async.commit_group;" ::: "memory")
#define CP_WAIT(n)  asm volatile("cp.async.wait_group %0;" :: "n"(n) : "memory")
#define LDSM4(r0, r1, r2, r3, addr) \
  asm volatile("ldmatrix.sync.aligned.m8n8.x4.shared.b16 {%0,%1,%2,%3}, [%4];" \
               : "=r"(r0), "=r"(r1), "=r"(r2), "=r"(r3) : "r"(addr))
#define LDSM4T(r0, r1, r2, r3, addr) \
  asm volatile("ldmatrix.sync.aligned.m8n8.x4.trans.shared.b16 {%0,%1,%2,%3}, [%4];" \
               : "=r"(r0), "=r"(r1), "=r"(r2), "=r"(r3) : "r"(addr))

__device__ __forceinline__ void mma16816(float* d, const uint32_t* a,
                                         const uint32_t* b) {
  asm volatile(
      "mma.sync.aligned.m16n8k16.row.col.f32.f16.f16.f32 "
      "{%0,%1,%2,%3}, {%4,%5,%6,%7}, {%8,%9}, {%0,%1,%2,%3};"
      : "+f"(d[0]), "+f"(d[1]), "+f"(d[2]), "+f"(d[3])
      : "r"(a[0]), "r"(a[1]), "r"(a[2]), "r"(a[3]), "r"(b[0]), "r"(b[1]));
}

__device__ __forceinline__ __half2 mk_h2(float a, float b) {
  return __halves2half2(__float2half(a), __float2half(b));
}

// ---------------- hidden fp32 -> fp16 ----------------
__global__ __launch_bounds__(256) void conv_kernel(
    const float* __restrict__ x, __half* __restrict__ h, int n4) {
  int i = blockIdx.x * 256 + threadIdx.x;
  if (i >= n4) return;
  float4 v = ((const float4*)x)[i];
  ((__half2*)h)[2 * i]     = mk_h2(v.x, v.y);
  ((__half2*)h)[2 * i + 1] = mk_h2(v.z, v.w);
}

// ---------------- transpose + scale(64) -> fp16 ----------------
__global__ __launch_bounds__(256) void tsplit_kernel(
    const float* __restrict__ W, __half* __restrict__ Th, int K, int N) {
  __shared__ float sm[32][33];
  int n0 = blockIdx.x * 32, k0 = blockIdx.y * 32;
  int tx = threadIdx.x & 31, ty = threadIdx.x >> 5;
  #pragma unroll
  for (int q = 0; q < 4; q++)
    sm[ty + 8 * q][tx] = W[(size_t)(k0 + ty + 8 * q) * N + n0 + tx];
  __syncthreads();
  #pragma unroll
  for (int q = 0; q < 4; q++) {
    float x = sm[tx][ty + 8 * q] * 64.0f;
    Th[(size_t)(n0 + ty + 8 * q) * K + k0 + tx] = __float2half(x);
  }
}

// ---------------- HMMA GEMM (1-pass fp16): C = escale * A * Bt^T ----------
constexpr int BM = 128, BN = 128, BKt = 32;
constexpr int AST = 40;
constexpr int PARTE = 128 * AST;
constexpr int G_BUFB = 2 * PARTE * 2;        // A + B per stage (bytes)
constexpr int G_SMEM = 2 * G_BUFB;           // 40960

__global__ __launch_bounds__(256, 2) void gemm_hmma(
    const __half* __restrict__ Ah, const __half* __restrict__ Bh,
    float* __restrict__ C, int M, int N, int K, float escale) {
  extern __shared__ __half smb[];
  const uint32_t sbase = smem_u32(smb);
  const int tid = threadIdx.x, lane = tid & 31, wid = tid >> 5;
  const int m0 = blockIdx.y * BM, n0 = blockIdx.x * BN;
  const int wm = (wid & 1) * 64, wn = (wid >> 1) * 32;

  float acc[4][4][4];
  #pragma unroll
  for (int i = 0; i < 4; i++)
    #pragma unroll
    for (int j = 0; j < 4; j++)
      #pragma unroll
      for (int q = 0; q < 4; q++) acc[i][j][q] = 0.0f;

  const int T = K / BKt;
  int ldr[2], ldc[2];
  #pragma unroll
  for (int i = 0; i < 2; i++) {
    int idx = tid + i * 256;
    ldr[i] = idx >> 2;
    ldc[i] = idx & 3;
  }

  #define ISSUE(t)                                                          \
    do {                                                                    \
      int k0_ = (t) * BKt;                                                  \
      uint32_t db_ = sbase + ((t) & 1) * G_BUFB;                            \
      _Pragma("unroll")                                                     \
      for (int i_ = 0; i_ < 2; i_++) {                                      \
        int r_ = ldr[i_], c_ = ldc[i_];                                     \
        uint32_t d_ = db_ + (r_ * AST + c_ * 8) * 2;                        \
        CP_ASYNC16(d_, Ah + (size_t)(m0 + r_) * K + k0_ + c_ * 8);          \
        CP_ASYNC16(d_ + PARTE * 2,                                          \
                   Bh + (size_t)(n0 + r_) * K + k0_ + c_ * 8);              \
      }                                                                     \
    } while (0)

  ISSUE(0);
  CP_COMMIT();

  for (int t = 0; t < T; t++) {
    if (t + 1 < T) {
      ISSUE(t + 1);
      CP_COMMIT();
      CP_WAIT(1);
    } else {
      CP_WAIT(0);
    }
    __syncthreads();

    uint32_t base = sbase + (t & 1) * G_BUFB;
    const uint32_t pA = base;
    const uint32_t pB = base + PARTE * 2;

    #pragma unroll
    for (int ks = 0; ks < 2; ks++) {
      const int kb = ks * 16;
      uint32_t a[4][4], b[4][2];
      #pragma unroll
      for (int mt = 0; mt < 4; mt++) {
        int r = wm + mt * 16 + (lane & 15);
        int c = kb + ((lane >> 4) << 3);
        LDSM4(a[mt][0], a[mt][1], a[mt][2], a[mt][3],
              pA + (uint32_t)(r * AST + c) * 2);
      }
      #pragma unroll
      for (int p = 0; p < 2; p++) {
        int g = lane >> 3;
        int r = wn + (p * 2 + (g >> 1)) * 8 + (lane & 7);
        int c = kb + ((g & 1) << 3);
        LDSM4(b[2 * p][0], b[2 * p][1], b[2 * p + 1][0], b[2 * p + 1][1],
              pB + (uint32_t)(r * AST + c) * 2);
      }
      #pragma unroll
      for (int mt = 0; mt < 4; mt++)
        #pragma unroll
        for (int nt = 0; nt < 4; nt++) mma16816(acc[mt][nt], a[mt], b[nt]);
    }
    __syncthreads();
  }
  #undef ISSUE

  #pragma unroll
  for (int mt = 0; mt < 4; mt++) {
    int row = m0 + wm + mt * 16 + (lane >> 2);
    #pragma unroll
    for (int nt = 0; nt < 4; nt++) {
      int col = n0 + wn + nt * 8 + ((lane & 3) << 1);
      *(float2*)&C[(size_t)row * N + col] =
          make_float2(acc[mt][nt][0] * escale, acc[mt][nt][1] * escale);
      *(float2*)&C[(size_t)(row + 8) * N + col] =
          make_float2(acc[mt][nt][2] * escale, acc[mt][nt][3] * escale);
    }
  }
}

// ---------------- inv_freq table ----------------
__global__ void invf_init() {
  int i = threadIdx.x;
  if (i < 128)
    g_invf[i] = exp(((double)(-2.0 * i) / 256.0) * 9.210340371976184);
}

// ---------------- RoPE: fp32 (64x) qkv -> head-major fp16 ----------------
__global__ __launch_bounds__(256) void rope_kernel(const int* __restrict__ pos) {
  int idx = blockIdx.x * 256 + threadIdx.x;
  int i   = idx & 127;
  int hh  = (idx >> 7) & 31;
  int row = idx >> 12;
  int p = pos[row];
  double ang = (double)p * g_invf[i];
  const double INV2PI = 0.15915494309189535;
  const double TWOPI  = 6.283185307179586;
  int kk = __double2int_rn(ang * INV2PI);
  float fr = (float)(ang - TWOPI * (double)kk);
  float s, c;
  __sincosf(fr, &s, &c);
  const float* base = g_qkv + (size_t)row * cQKV + hh * cHD;
  const float inv64 = 1.0f / 64.0f;
  float x1 = base[i], x2 = base[i + 128];
  float y1 = (x1 * c - x2 * s) * inv64;
  float y2 = (x2 * c + x1 * s) * inv64;
  int b = row >> 11, sidx = row & 2047;
  bool isq = hh < 16;
  int head = isq ? hh : hh - 16;
  size_t o = ((size_t)(b * cNH + head) * cS + sidx) * cHD + i;
  if (isq) {
    y1 *= 0.0625f;
    y2 *= 0.0625f;
    g_qh[o]       = __float2half(y1);
    g_qh[o + 128] = __float2half(y2);
  } else {
    g_kh[o]       = __float2half(y1);
    g_kh[o + 128] = __float2half(y2);
  }
}

// ---------------- V: fp32 (64x) -> head-major fp16 ----------------
__global__ __launch_bounds__(256) void vsplit_kernel() {
  int idx = blockIdx.x * 256 + threadIdx.x;
  int d4 = idx & 63;
  int h  = (idx >> 6) & 15;
  int row = idx >> 10;
  int b = row >> 11, sidx = row & 2047;
  const float inv64 = 1.0f / 64.0f;
  float4 v = *(const float4*)(g_qkv + (size_t)row * cQKV + 2 * cQSZ + h * cHD +
                              d4 * 4);
  size_t o = ((size_t)(b * cNH + h) * cS + sidx) * cHD + d4 * 4;
  *(__half2*)(g_vh + o)     = mk_h2(v.x * inv64, v.y * inv64);
  *(__half2*)(g_vh + o + 2) = mk_h2(v.z * inv64, v.w * inv64);
}

// ---------------- HMMA flash attention (fp16, 1-pass QK and PV) ----------
constexpr int FQST = 264;
constexpr int FPST = 72;
constexpr int F_QH = 0;
constexpr int F_KH = 1 * 64 * FQST;
constexpr int F_VH = 2 * 64 * FQST;
constexpr int F_PH = 3 * 64 * FQST;
constexpr int F_TOT = F_PH + 64 * FPST;
constexpr int FLASH_SMEM = F_TOT * 2 + 448 * 4;   // 112384 B

__global__ __launch_bounds__(256, 1) void flash_hmma(__half* __restrict__ ath) {
  extern __shared__ __half smem[];
  const uint32_t sb = smem_u32(smem);
  float* fre  = (float*)(smem + F_TOT);
  float* m_s  = fre;
  float* l_s  = fre + 64;
  float* f_s  = fre + 128;
  float* rmax = fre + 192;
  float* rsum = fre + 320;

  const int qtile = gridDim.x - 1 - blockIdx.x;
  const int bh = blockIdx.y;
  const int b = bh >> 4, h = bh & 15;
  const int tid = threadIdx.x, lane = tid & 31, wid = tid >> 5;
  const int wm = wid & 3, wg = wid >> 2;
  const int q0 = qtile * 64;

  const __half* qhb = g_qh + ((size_t)bh * cS + q0) * cHD;
  const __half* khb = g_kh + (size_t)bh * cS * cHD;
  const __half* vhb = g_vh + (size_t)bh * cS * cHD;

  #define LOADP(gptr, soff)                                              \
    do {                                                                 \
      _Pragma("unroll")                                                  \
      for (int i_ = 0; i_ < 8; i_++) {                                   \
        int id_ = tid + 256 * i_;                                        \
        int r_ = id_ >> 5, c_ = id_ & 31;                                \
        CP_ASYNC16(sb + (uint32_t)((soff) + r_ * FQST + c_ * 8) * 2,     \
                   (gptr) + r_ * 256 + c_ * 8);                          \
      }                                                                  \
    } while (0)

  LOADP(qhb, F_QH);
  LOADP(khb, F_KH);
  CP_COMMIT();
  LOADP(vhb, F_VH);
  CP_COMMIT();

  if (tid < 64) { m_s[tid] = -1e30f; l_s[tid] = 0.0f; }

  float o[16][4];
  #pragma unroll
  for (int i = 0; i < 16; i++)
    #pragma unroll
    for (int j = 0; j < 4; j++) o[i][j] = 0.0f;

  const uint32_t pQh = sb + F_QH * 2;
  const uint32_t pKh = sb + F_KH * 2;
  const uint32_t pVh = sb + F_VH * 2;
  const uint32_t pPh = sb + F_PH * 2;

  const int arow = 16 * wm + (lane & 15);
  const int acol = (lane >> 4) * 8;
  const int brow = wg * 32 + (lane & 7) + (lane >> 4) * 8;
  const int bcol = ((lane >> 3) & 1) * 8;
  const int row0 = 16 * wm + (lane >> 2);

  for (int jt = 0; jt <= qtile; jt++) {
    CP_WAIT(1);
    __syncthreads();

    // ---- S = Q K^T (1 pass) ----
    float s[4][4];
    #pragma unroll
    for (int nt = 0; nt < 4; nt++)
      #pragma unroll
      for (int c = 0; c < 4; c++) s[nt][c] = 0.0f;

    #pragma unroll 4
    for (int ks = 0; ks < 16; ks++) {
      const int k0 = ks * 16;
      uint32_t aqh[4], bkh0[4], bkh1[4];
      LDSM4(aqh[0], aqh[1], aqh[2], aqh[3],
            pQh + (uint32_t)(arow * FQST + k0 + acol) * 2);
      uint32_t boff0 = (uint32_t)(brow * FQST + k0 + bcol) * 2;
      LDSM4(bkh0[0], bkh0[1], bkh0[2], bkh0[3], pKh + boff0);
      LDSM4(bkh1[0], bkh1[1], bkh1[2], bkh1[3],
            pKh + boff0 + 16 * FQST * 2);
      uint32_t* bhp[4] = {&bkh0[0], &bkh0[2], &bkh1[0], &bkh1[2]};
      #pragma unroll
      for (int nt = 0; nt < 4; nt++) mma16816(s[nt], aqh, bhp[nt]);
    }

    // ---- causal mask ----
    if (jt == qtile) {
      #pragma unroll
      for (int nt = 0; nt < 4; nt++)
        #pragma unroll
        for (int c = 0; c < 4; c++) {
          int kvloc = wg * 32 + nt * 8 + (lane & 3) * 2 + (c & 1);
          int qloc = 16 * wm + (lane >> 2) + 8 * (c >> 1);
          if (kvloc > qloc) s[nt][c] = -1e30f;
        }
    }

    // ---- row max ----
    float lm0 = -1e30f, lm1 = -1e30f;
    #pragma unroll
    for (int nt = 0; nt < 4; nt++) {
      lm0 = fmaxf(lm0, fmaxf(s[nt][0], s[nt][1]));
      lm1 = fmaxf(lm1, fmaxf(s[nt][2], s[nt][3]));
    }
    lm0 = fmaxf(lm0, __shfl_xor_sync(0xffffffffu, lm0, 1));
    lm0 = fmaxf(lm0, __shfl_xor_sync(0xffffffffu, lm0, 2));
    lm1 = fmaxf(lm1, __shfl_xor_sync(0xffffffffu, lm1, 1));
    lm1 = fmaxf(lm1, __shfl_xor_sync(0xffffffffu, lm1, 2));
    if ((lane & 3) == 0) {
      rmax[wg * 64 + row0] = lm0;
      rmax[wg * 64 + row0 + 8] = lm1;
    }
    __syncthreads();
    if (tid < 64) {
      float mo = m_s[tid];
      float mn = fmaxf(mo, fmaxf(rmax[tid], rmax[64 + tid]));
      f_s[tid] = __expf(mo - mn);
      m_s[tid] = mn;
    }
    __syncthreads();

    // ---- exp, P store (fp16), O rescale, row sums ----
    {
      float mn0 = m_s[row0], mn1 = m_s[row0 + 8];
      float sum0 = 0.0f, sum1 = 0.0f;
      #pragma unroll
      for (int nt = 0; nt < 4; nt++) {
        float p0 = __expf(s[nt][0] - mn0);
        float p1 = __expf(s[nt][1] - mn0);
        float p2 = __expf(s[nt][2] - mn1);
        float p3 = __expf(s[nt][3] - mn1);
        sum0 += p0 + p1;
        sum1 += p2 + p3;
        int col = wg * 32 + nt * 8 + (lane & 3) * 2;
        *(__half2*)(smem + F_PH + row0 * FPST + col) = mk_h2(p0, p1);
        *(__half2*)(smem + F_PH + (row0 + 8) * FPST + col) = mk_h2(p2, p3);
      }
      sum0 += __shfl_xor_sync(0xffffffffu, sum0, 1);
      sum0 += __shfl_xor_sync(0xffffffffu, sum0, 2);
      sum1 += __shfl_xor_sync(0xffffffffu, sum1, 1);
      sum1 += __shfl_xor_sync(0xffffffffu, sum1, 2);
      if ((lane & 3) == 0) {
        rsum[wg * 64 + row0] = sum0;
        rsum[wg * 64 + row0 + 8] = sum1;
      }
      float f0 = f_s[row0], f1 = f_s[row0 + 8];
      #pragma unroll
      for (int dt = 0; dt < 16; dt++) {
        o[dt][0] *= f0; o[dt][1] *= f0;
        o[dt][2] *= f1; o[dt][3] *= f1;
      }
    }

    CP_WAIT(0);
    __syncthreads();

    if (jt < qtile) {
      LOADP(khb + (jt + 1) * 64 * 256, F_KH);
      CP_COMMIT();
    }
    if (tid < 64) l_s[tid] = l_s[tid] * f_s[tid] + rsum[tid] + rsum[64 + tid];

    // ---- O += P V (1 pass) ----
    #pragma unroll
    for (int ks = 0; ks < 4; ks++) {
      const int k0 = ks * 16;
      uint32_t aph[4];
      LDSM4(aph[0], aph[1], aph[2], aph[3],
            pPh + (uint32_t)(arow * FPST + k0 + acol) * 2);
      const int vrow = k0 + (lane & 15);
      #pragma unroll
      for (int dt2 = 0; dt2 < 8; dt2++) {
        int dbase = wg * 128 + dt2 * 16 + (lane >> 4) * 8;
        uint32_t bvh[4];
        LDSM4T(bvh[0], bvh[1], bvh[2], bvh[3],
               pVh + (uint32_t)(vrow * FQST + dbase) * 2);
        mma16816(o[dt2 * 2], aph, &bvh[0]);
        mma16816(o[dt2 * 2 + 1], aph, &bvh[2]);
      }
    }
    __syncthreads();
    if (jt < qtile) {
      LOADP(vhb + (jt + 1) * 64 * 256, F_VH);
      CP_COMMIT();
    }
  }
  #undef LOADP

  // ---- epilogue: /l, write fp16 to [b,s,h*256+d] ----
  float rl0 = 1.0f / l_s[row0];
  float rl1 = 1.0f / l_s[row0 + 8];
  size_t g0 = ((size_t)(b * cS + q0 + row0)) * cQSZ + h * cHD;
  size_t g1 = g0 + 8 * cQSZ;
  #pragma unroll
  for (int dt = 0; dt < 16; dt++) {
    int col = wg * 128 + dt * 8 + (lane & 3) * 2;
    *(__half2*)(ath + g0 + col) = mk_h2(o[dt][0] * rl0, o[dt][1] * rl0);
    *(__half2*)(ath + g1 + col) = mk_h2(o[dt][2] * rl1, o[dt][3] * rl1);
  }
}

// ---------------- launch ----------------
extern "C" void kernel_launch(void* const* d_in, const int* in_sizes, int n_in,
                              void* d_out, int out_size) {
  (void)in_sizes; (void)n_in; (void)out_size;
  const float* hidden = (const float*)d_in[0];
  const int*   pos    = (const int*)d_in[1];
  const float* Wqkv   = (const float*)d_in[2];
  const float* Wo     = (const float*)d_in[3];
  float* out = (float*)d_out;

  float* qkv_p;
  __half *hidh, *w1h, *ath, *w2h;
  cudaGetSymbolAddress((void**)&qkv_p, g_qkv);
  cudaGetSymbolAddress((void**)&hidh, g_hid_h);
  cudaGetSymbolAddress((void**)&w1h, g_w1_h);
  cudaGetSymbolAddress((void**)&ath, g_at_h);
  cudaGetSymbolAddress((void**)&w2h, g_w2_h);

  cudaFuncSetAttribute(gemm_hmma,
                       cudaFuncAttributeMaxDynamicSharedMemorySize, G_SMEM);
  cudaFuncSetAttribute(flash_hmma,
                       cudaFuncAttributeMaxDynamicSharedMemorySize, FLASH_SMEM);

  invf_init<<<1, 128>>>();
  {
    int n4 = cM * cH / 4;
    conv_kernel<<<(n4 + 255) / 256, 256>>>(hidden, hidh, n4);
    tsplit_kernel<<<dim3(cQKV / 32, cH / 32), 256>>>(Wqkv, w1h, cH, cQKV);
    tsplit_kernel<<<dim3(cH / 32, cQSZ / 32), 256>>>(Wo, w2h, cQSZ, cH);
  }
  // QKV projection: 1 pass. C = 64 * qkv.
  gemm_hmma<<<dim3(cQKV / BN, cM / BM), 256, G_SMEM>>>(
      hidh, w1h, qkv_p, cM, cQKV, cH, 1.0f);
  rope_kernel<<<(cM * 32 * 128) / 256, 256>>>(pos);
  vsplit_kernel<<<(cM * cQSZ / 4) / 256, 256>>>();
  flash_hmma<<<dim3(cS / 64, cB * cNH), 256, FLASH_SMEM>>>(ath);
  // output projection: 1 pass. C = 64 * out -> /64.
  gemm_hmma<<<dim3(cH / BN, cM / BM), 256, G_SMEM>>>(
      ath, w2h, out, cM, cH, cQSZ, 1.0f / 64.0f);
}